// round 13
// baseline (speedup 1.0000x reference)
#include <cuda_runtime.h>
#include <cuda_bf16.h>
#include <cstdint>
#include <math.h>

// Problem dims
#define BB   256
#define TT   200
#define DD   311
#define UU   256
#define G3   768          // 3*U
#define NOUT 19
#define BT   (BB*TT)      // 51200

typedef unsigned long long u64;

// ---------------- packed f32x2 helpers (Blackwell PTX) ---------------------
__device__ __forceinline__ u64 splat2(float v) {
    u64 r; unsigned u = __float_as_uint(v);
    asm("mov.b64 %0, {%1, %1};" : "=l"(r) : "r"(u));
    return r;
}
__device__ __forceinline__ void ffma2(u64& d, u64 a, u64 b) {
    asm("fma.rn.f32x2 %0, %1, %2, %0;" : "+l"(d) : "l"(a), "l"(b));
}
__device__ __forceinline__ float lo2(u64 v) {
    return __uint_as_float((unsigned)(v & 0xffffffffull));
}
__device__ __forceinline__ float hi2(u64 v) {
    return __uint_as_float((unsigned)(v >> 32));
}

// ---------------- cp.async / smem helpers ----------------------------------
__device__ __forceinline__ unsigned smem_u32(const void* p) {
    unsigned r;
    asm("{ .reg .u64 t; cvta.to.shared.u64 t, %1; cvt.u32.u64 %0, t; }"
        : "=r"(r) : "l"(p));
    return r;
}
#define CP16(dst, src) \
    asm volatile("cp.async.cg.shared.global [%0], [%1], 16;" :: "r"(dst), "l"(src))
#define CP4(dst, src) \
    asm volatile("cp.async.ca.shared.global [%0], [%1], 4;" :: "r"(dst), "l"(src))
#define CPCOMMIT() asm volatile("cp.async.commit_group;")
#define CPWAIT1()  asm volatile("cp.async.wait_group 1;" ::: "memory")

// ---------------- cluster / mbarrier helpers -------------------------------
__device__ __forceinline__ unsigned mapa_clu(unsigned addr, unsigned rank) {
    unsigned r;
    asm("mapa.shared::cluster.u32 %0, %1, %2;" : "=r"(r) : "r"(addr), "r"(rank));
    return r;
}
#define MBAR_INIT(a, n) \
    asm volatile("mbarrier.init.shared.b64 [%0], %1;" :: "r"(a), "r"(n) : "memory")
// CLUSTER-scope release: orders prior st.shared::cluster stores before the
// arrival becomes observable (the cta-scope default was the R12 bug).
#define MBAR_ARRIVE_CLU(peer_a) \
    asm volatile("mbarrier.arrive.release.cluster.shared::cluster.b64 _, [%0];" \
        :: "r"(peer_a) : "memory")
// CLUSTER-scope acquire on the wait side (pairs with the release above).
#define MBAR_WAIT_PAR(a, par) do {                                        \
    unsigned _done;                                                        \
    do {                                                                   \
        asm volatile("{\n\t.reg .pred p;\n\t"                              \
            "mbarrier.try_wait.parity.acquire.cluster.shared::cta.b64 p, [%1], %2;\n\t" \
            "selp.b32 %0, 1, 0, p;\n\t}"                                   \
            : "=r"(_done) : "r"(a), "r"(par) : "memory");                  \
        if (!_done) __nanosleep(20);                                       \
    } while (!_done);                                                      \
} while (0)
#define ST_CLU_V4(a, v0, v1, v2, v3) \
    asm volatile("st.shared::cluster.v4.b32 [%0], {%1,%2,%3,%4};" \
        :: "r"(a), "r"(v0), "r"(v1), "r"(v2), "r"(v3) : "memory")
#define CLUSTER_SYNC_() do { \
    asm volatile("barrier.cluster.arrive.aligned;" ::: "memory"); \
    asm volatile("barrier.cluster.wait.aligned;" ::: "memory"); } while (0)

// ---------------- scratch (device globals; no cudaMalloc allowed) ----------
__device__ float g_xp[2][(size_t)BT * G3];   // input projections, per direction
__device__ float g_y [2][(size_t)BT * UU];   // hidden sequences
__device__ int   g_mask[BT];
__device__ float g_rkp2[2 * 8 * 96 * 256];   // rk col-major [dir][cc][col][k]
__device__ float g_b1p[2 * 8 * 96];          // recurrent bias per (dir, cc)

// fast, accurate-enough gate functions (rel err ~2^-21)
__device__ __forceinline__ float fsig(float v) {
    return __fdividef(1.0f, 1.0f + __expf(-v));
}
__device__ __forceinline__ float ftanh(float v) {
    return 1.0f - __fdividef(2.0f, __expf(2.0f * v) + 1.0f);
}

// ---------------- mask: mask[b,t] = any(x[b,t,:] != 0) ---------------------
__global__ __launch_bounds__(256) void mask_kernel(const float* __restrict__ x) {
    int warp = (blockIdx.x * blockDim.x + threadIdx.x) >> 5;
    int lane = threadIdx.x & 31;
    if (warp >= BT) return;
    const float* row = x + (size_t)warp * DD;
    int any = 0;
    for (int i = lane; i < DD; i += 32) any |= (row[i] != 0.0f);
    unsigned b = __ballot_sync(0xffffffffu, any);
    if (lane == 0) g_mask[warp] = (b != 0u);
}

// ---------------- weight pre-pack: col-major per (dir, unit-chunk) ---------
__global__ __launch_bounds__(256) void pack_kernel(
    const float* __restrict__ rk_f, const float* __restrict__ rk_b,
    const float* __restrict__ b_f,  const float* __restrict__ b_b)
{
    int i = blockIdx.x * blockDim.x + threadIdx.x;
    const int total = 2 * 8 * 96 * 256;
    if (i < total) {
        int k     = i & 255;
        int rest  = i >> 8;
        int c     = rest % 96;
        int slice = rest / 96;          // 0..15
        int cc    = slice & 7;
        int dir   = slice >> 3;
        const float* rk = dir ? rk_b : rk_f;
        g_rkp2[i] = rk[(size_t)k * G3 + (c >> 5) * UU + cc * 32 + (c & 31)];
    }
    if (i < 2 * 8 * 96) {
        int c   = i % 96;
        int cc  = (i / 96) & 7;
        int dir = i / (96 * 8);
        const float* b = dir ? b_b : b_f;
        g_b1p[i] = b[G3 + (c >> 5) * UU + cc * 32 + (c & 31)];
    }
}

// ---------------- phase 1: xp[m,n] = sum_k x[m,k]*W[k,n] + b0[n] -----------
// M=51200, K=311, N=768.  128x128x8 tile, 256 thr, 8x8 per-thread (f32x2),
// double-buffered smem with register prefetch.
#define NKT 39   // ceil(311/8)

__global__ __launch_bounds__(256) void proj_kernel(
    const float* __restrict__ x,
    const float* __restrict__ k_f, const float* __restrict__ b_f,
    const float* __restrict__ k_b, const float* __restrict__ b_b)
{
    __shared__ float As[2][8 * 132];
    __shared__ float Bs[2][8 * 132];

    const int dir = blockIdx.z;
    const float* W    = dir ? k_b : k_f;
    const float* bias = dir ? b_b : b_f;       // row 0 = input bias
    float* xp = g_xp[dir];

    const int m0 = blockIdx.y * 128;
    const int n0 = blockIdx.x * 128;
    const int tid = threadIdx.x;
    const int tx = tid & 15;
    const int ty = tid >> 4;

    const int lxm = tid >> 1;            // 0..127
    const int lxk = (tid & 1) * 4;       // 0 or 4
    const int lbk = tid >> 5;            // 0..7
    const int lbn = (tid & 31) * 4;      // 0..124

    float  xa[4];
    float4 wb;

    auto load_tile = [&](int k0) {
#pragma unroll
        for (int j = 0; j < 4; j++) {
            int k = k0 + lxk + j;
            xa[j] = (k < DD) ? __ldg(&x[(size_t)(m0 + lxm) * DD + k]) : 0.0f;
        }
        if (k0 + lbk < DD)
            wb = *(const float4*)&W[(size_t)(k0 + lbk) * G3 + n0 + lbn];
        else
            wb = make_float4(0.f, 0.f, 0.f, 0.f);
    };

    u64 acc2[8][4];
#pragma unroll
    for (int i = 0; i < 8; i++)
#pragma unroll
        for (int j = 0; j < 4; j++) acc2[i][j] = 0ull;

    load_tile(0);
#pragma unroll
    for (int j = 0; j < 4; j++) As[0][(lxk + j) * 132 + lxm] = xa[j];
    *(float4*)&Bs[0][lbk * 132 + lbn] = wb;
    __syncthreads();

    for (int tIdx = 0; tIdx < NKT; tIdx++) {
        const int cur = tIdx & 1;
        if (tIdx + 1 < NKT) load_tile((tIdx + 1) * 8);

#pragma unroll
        for (int kk = 0; kk < 8; kk++) {
            float4 a0 = *(float4*)&As[cur][kk * 132 + ty * 4];
            float4 a1 = *(float4*)&As[cur][kk * 132 + 64 + ty * 4];
            const u64* bp0 = (const u64*)&Bs[cur][kk * 132 + tx * 4];
            const u64* bp1 = (const u64*)&Bs[cur][kk * 132 + 64 + tx * 4];
            u64 bv[4] = {bp0[0], bp0[1], bp1[0], bp1[1]};
            float av[8] = {a0.x, a0.y, a0.z, a0.w, a1.x, a1.y, a1.z, a1.w};
#pragma unroll
            for (int i = 0; i < 8; i++) {
                u64 asp = splat2(av[i]);
#pragma unroll
                for (int j = 0; j < 4; j++) ffma2(acc2[i][j], asp, bv[j]);
            }
        }

        if (tIdx + 1 < NKT) {
            __syncthreads();
#pragma unroll
            for (int j = 0; j < 4; j++)
                As[cur ^ 1][(lxk + j) * 132 + lxm] = xa[j];
            *(float4*)&Bs[cur ^ 1][lbk * 132 + lbn] = wb;
            __syncthreads();
        }
    }

#pragma unroll
    for (int i = 0; i < 8; i++) {
        int row = m0 + ((i < 4) ? (ty * 4 + i) : (64 + ty * 4 + i - 4));
        float* o = &xp[(size_t)row * G3 + n0];
#pragma unroll
        for (int jh = 0; jh < 2; jh++) {
            int c0 = jh * 64 + tx * 4;
            float4 v;
            v.x = lo2(acc2[i][jh * 2 + 0]) + __ldg(&bias[n0 + c0 + 0]);
            v.y = hi2(acc2[i][jh * 2 + 0]) + __ldg(&bias[n0 + c0 + 1]);
            v.z = lo2(acc2[i][jh * 2 + 1]) + __ldg(&bias[n0 + c0 + 2]);
            v.w = hi2(acc2[i][jh * 2 + 1]) + __ldg(&bias[n0 + c0 + 3]);
            *(float4*)&o[c0] = v;
        }
    }
}

// ---------------- phase 2: persistent cluster scan with DSMEM h-push -------
// grid (8,16), cluster (8,1,1): blockIdx.x = cc = cluster rank (unit chunk),
// blockIdx.y = dir*8 + bg. Co-residency of the 8 CTAs is HW-guaranteed, the
// 16 clusters are independent -> deadlock-free. 200 steps per launch.
// h exchange: each CTA pushes its 32x32 h chunk into ALL 8 CTAs' smem
// (mapa + st.shared::cluster), double-buffered by step parity; sync is one
// mbarrier (8 arrivals) per CTA per step with release.cluster/acquire.cluster
// semantics (the R12 bug was cta-scope fencing on cluster-scope stores).
#define KS 260
#define SCC_FLOATS (4 + 96 * KS + 2 * 32 * KS + 32 * 100 + 2 * 3072 + 96 + 64)
#define SCC_BYTES  (SCC_FLOATS * 4)

__global__ __launch_bounds__(256, 1) __cluster_dims__(8, 1, 1)
void scan_dsmem()
{
    extern __shared__ float sm[];
    // [0..4) floats: mbarrier (u64) + pad
    float* rs2  = sm + 4;                 // [96][260] rk slice, col-major
    float* hs0  = rs2 + 96 * KS;          // h buffer, parity 0
    float* hs1  = hs0 + 32 * KS;          // h buffer, parity 1
    float* recs = hs1 + 32 * KS;          // [32][100] rec + b1
    float* xpb  = recs + 32 * 100;        // [2][32][96] xp double buffer
    float* b1s  = xpb + 2 * 3072;         // [96]
    int*   mkv  = (int*)(b1s + 96);       // [2][32]

    const unsigned mbar  = smem_u32(sm);
    const unsigned xpb_a = smem_u32(xpb);
    const unsigned mkv_a = smem_u32(mkv);
    const unsigned hs0_a = smem_u32(hs0);
    const unsigned hs1_a = smem_u32(hs1);

    const int tid = threadIdx.x;
    const int cc  = blockIdx.x;           // cluster rank 0..7
    const int grp = blockIdx.y;           // 0..15
    const int bg  = grp & 7;
    const int dir = grp >> 3;
    const int u0  = cc * 32;
    const int b0  = bg * 32;

    float*       y  = g_y[dir];
    const float* xp = g_xp[dir];

    // ---- one-time fills ----
    if (tid == 0) MBAR_INIT(mbar, 8);
    {   // rk slice: packed contiguous [96][256] -> smem stride-260 col-major
        const float4* src =
            (const float4*)(g_rkp2 + (size_t)(dir * 8 + cc) * 96 * 256);
#pragma unroll
        for (int i = 0; i < 24; i++) {
            int idx = tid + 256 * i;      // 96*64 = 6144 quads
            int c = idx >> 6, q = idx & 63;
            *(float4*)&rs2[c * KS + 4 * q] = src[idx];
        }
    }
    if (tid < 96) b1s[tid] = g_b1p[(dir * 8 + cc) * 96 + tid];
    for (int i = tid; i < 32 * KS; i += 256) hs0[i] = 0.0f;   // h0 = 0

    // xp/mask prefetch for timestep tn into buffer buf
    auto prefetch = [&](int tn, int buf) {
        unsigned dbase = xpb_a + (unsigned)(buf * 3072) * 4u;
#pragma unroll
        for (int it = 0; it < 3; it++) {
            int j = tid + 256 * it;       // 0..767, 16B each
            int p = j >> 3, o = j & 7;
            int row = p / 3, seg = p - 3 * row;
            const float* src =
                xp + ((size_t)(b0 + row) * TT + tn) * G3 + seg * UU + u0 + o * 4;
            CP16(dbase + (unsigned)(row * 96 + seg * 32 + o * 4) * 4u, src);
        }
        if (tid < 32)
            CP4(mkv_a + (unsigned)(buf * 32 + tid) * 4u,
                &g_mask[(b0 + tid) * TT + tn]);
    };

    prefetch(dir ? (TT - 1) : 0, 0);
    CPCOMMIT();
    __syncthreads();
    CLUSTER_SYNC_();                      // peers' mbarriers initialized

    const int rt = tid & 15;              // GEMM rows {rt, rt+16}
    const int ct = tid >> 4;              // cols 6ct..6ct+5
    const float* wp = &rs2[(6 * ct) * KS];

    // gate mapping: one row, 4 consecutive units per thread
    const int gr = tid >> 3;              // 0..31 row
    const int gu = (tid & 7) * 4;         // 0,4,...,28

    int ph = 0;

    for (int s = 0; s < TT; s++) {
        const int t = dir ? (TT - 1 - s) : s;

        if (s + 1 < TT) prefetch(dir ? (t - 1) : (t + 1), (s + 1) & 1);
        CPCOMMIT();

        if (s > 0) {                      // all 8 h chunks for this step landed
            MBAR_WAIT_PAR(mbar, ph);
            ph ^= 1;
        }

        const float* hb = (s & 1) ? hs1 : hs0;

        // ---- GEMM 32x96x256, k-paired f32x2 (2 rows x 6 cols / thread) ----
        u64 acc[2][6];
#pragma unroll
        for (int i = 0; i < 2; i++)
#pragma unroll
            for (int j = 0; j < 6; j++) acc[i][j] = 0ull;

        const float* h0p = &hb[rt * KS];
        const float* h1p = &hb[(rt + 16) * KS];

#pragma unroll 2
        for (int k0 = 0; k0 < 256; k0 += 4) {
            ulonglong2 ha = *(const ulonglong2*)(h0p + k0);
            ulonglong2 hc = *(const ulonglong2*)(h1p + k0);
#pragma unroll
            for (int j = 0; j < 6; j++) {
                ulonglong2 w = *(const ulonglong2*)(wp + j * KS + k0);
                ffma2(acc[0][j], ha.x, w.x);
                ffma2(acc[0][j], ha.y, w.y);
                ffma2(acc[1][j], hc.x, w.x);
                ffma2(acc[1][j], hc.y, w.y);
            }
        }

#pragma unroll
        for (int i = 0; i < 2; i++) {
            int row = rt + 16 * i;
#pragma unroll
            for (int j = 0; j < 6; j++)
                recs[row * 100 + 6 * ct + j] =
                    lo2(acc[i][j]) + hi2(acc[i][j]) + b1s[6 * ct + j];
        }
        CPWAIT1();                        // xp buf[s&1] landed
        __syncthreads();                  // publish recs + cp.async data

        // ---- gates: 1 row x 4 units per thread, then DSMEM push ----
        {
            const float* xb = &xpb[(s & 1) * 3072];
            float4 rz = *(float4*)&recs[gr * 100 + gu];
            float4 rr = *(float4*)&recs[gr * 100 + 32 + gu];
            float4 rh = *(float4*)&recs[gr * 100 + 64 + gu];
            float4 xz = *(const float4*)&xb[gr * 96 + gu];
            float4 xr = *(const float4*)&xb[gr * 96 + 32 + gu];
            float4 xh = *(const float4*)&xb[gr * 96 + 64 + gu];
            float4 hp = *(const float4*)&hb[gr * KS + u0 + gu];
            int msk = mkv[(s & 1) * 32 + gr];

            float4 hn;
            {
                float z0 = fsig(xz.x + rz.x), z1 = fsig(xz.y + rz.y);
                float z2 = fsig(xz.z + rz.z), z3 = fsig(xz.w + rz.w);
                float r0 = fsig(xr.x + rr.x), r1 = fsig(xr.y + rr.y);
                float r2 = fsig(xr.z + rr.z), r3 = fsig(xr.w + rr.w);
                float h0 = ftanh(xh.x + r0 * rh.x), h1 = ftanh(xh.y + r1 * rh.y);
                float h2 = ftanh(xh.z + r2 * rh.z), h3 = ftanh(xh.w + r3 * rh.w);
                hn.x = z0 * hp.x + (1.0f - z0) * h0;
                hn.y = z1 * hp.y + (1.0f - z1) * h1;
                hn.z = z2 * hp.z + (1.0f - z2) * h2;
                hn.w = z3 * hp.w + (1.0f - z3) * h3;
            }
            if (!msk) hn = hp;

            // global y (for dense phase; off critical path)
            *(float4*)&y[((size_t)(b0 + gr) * TT + t) * UU + u0 + gu] = hn;

            // push into all 8 CTAs' next-parity h buffer
            if (s + 1 < TT) {
                unsigned base = ((s & 1) ? hs0_a : hs1_a) +
                                (unsigned)(gr * KS + u0 + gu) * 4u;
                unsigned v0 = __float_as_uint(hn.x);
                unsigned v1 = __float_as_uint(hn.y);
                unsigned v2 = __float_as_uint(hn.z);
                unsigned v3 = __float_as_uint(hn.w);
#pragma unroll
                for (int r = 0; r < 8; r++) {
                    unsigned pa = mapa_clu(base, (unsigned)r);
                    ST_CLU_V4(pa, v0, v1, v2, v3);
                }
            }
        }

        __syncthreads();                  // all pushes issued before arrives
        if (s + 1 < TT && tid < 8) {
            unsigned pb = mapa_clu(mbar, (unsigned)tid);
            MBAR_ARRIVE_CLU(pb);          // release.cluster: orders the pushes
        }
    }

    CLUSTER_SYNC_();                      // clean cluster exit
}

// ---------------- phase 3: dense + softmax ---------------------------------
__global__ __launch_bounds__(256) void dense_kernel(
    const float* __restrict__ w_d, const float* __restrict__ b_d,
    float* __restrict__ out)
{
    __shared__ float ws[2 * UU * NOUT];   // 512*19
    __shared__ float bs[NOUT];
    for (int i = threadIdx.x; i < 2 * UU * NOUT; i += 256) ws[i] = w_d[i];
    if (threadIdx.x < NOUT) bs[threadIdx.x] = b_d[threadIdx.x];
    __syncthreads();

    int warp = threadIdx.x >> 5, lane = threadIdx.x & 31;
    int row = blockIdx.x * 8 + warp;               // 6400 * 8 = 51200 exact
    const float* hf = g_y[0] + (size_t)row * UU;
    const float* hb = g_y[1] + (size_t)row * UU;

    float acc[NOUT];
#pragma unroll
    for (int o = 0; o < NOUT; o++) acc[o] = 0.0f;

    for (int j = lane; j < UU; j += 32) {
        float a = hf[j];
        const float* w = &ws[j * NOUT];
#pragma unroll
        for (int o = 0; o < NOUT; o++) acc[o] += a * w[o];
        float b = hb[j];
        const float* w2 = &ws[(UU + j) * NOUT];
#pragma unroll
        for (int o = 0; o < NOUT; o++) acc[o] += b * w2[o];
    }
#pragma unroll
    for (int off = 16; off > 0; off >>= 1)
#pragma unroll
        for (int o = 0; o < NOUT; o++)
            acc[o] += __shfl_xor_sync(0xffffffffu, acc[o], off);

#pragma unroll
    for (int o = 0; o < NOUT; o++) acc[o] += bs[o];
    float m = acc[0];
#pragma unroll
    for (int o = 1; o < NOUT; o++) m = fmaxf(m, acc[o]);
    float sum = 0.0f;
#pragma unroll
    for (int o = 0; o < NOUT; o++) { acc[o] = expf(acc[o] - m); sum += acc[o]; }
    float inv = 1.0f / sum;

    if (lane < NOUT) {
        float v = 0.0f;
#pragma unroll
        for (int o = 0; o < NOUT; o++) if (lane == o) v = acc[o];
        out[(size_t)row * NOUT + lane] = v * inv;
    }
}

// ---------------- launch ----------------------------------------------------
extern "C" void kernel_launch(void* const* d_in, const int* in_sizes, int n_in,
                              void* d_out, int out_size)
{
    const float* x    = (const float*)d_in[0];
    const float* k_f  = (const float*)d_in[1];
    const float* rk_f = (const float*)d_in[2];
    const float* b_f  = (const float*)d_in[3];
    const float* k_b  = (const float*)d_in[4];
    const float* rk_b = (const float*)d_in[5];
    const float* b_b  = (const float*)d_in[6];
    const float* w_d  = (const float*)d_in[7];
    const float* b_d  = (const float*)d_in[8];
    float* out = (float*)d_out;

    // mask + weight pack + input projections
    mask_kernel<<<BT / 8, 256>>>(x);
    pack_kernel<<<(2 * 8 * 96 * 256) / 256, 256>>>(rk_f, rk_b, b_f, b_b);
    dim3 pg(G3 / 128, BT / 128, 2);
    proj_kernel<<<pg, 256>>>(x, k_f, b_f, k_b, b_b);

    // persistent DSMEM-cluster scan (16 independent 8-CTA clusters)
    cudaFuncSetAttribute(scan_dsmem,
                         cudaFuncAttributeMaxDynamicSharedMemorySize,
                         SCC_BYTES);
    dim3 sg(8, 16, 1);
    scan_dsmem<<<sg, 256, SCC_BYTES>>>();

    // dense + softmax
    dense_kernel<<<BT / 8, 256>>>(w_d, b_d, out);
}

// round 14
// speedup vs baseline: 1.3988x; 1.3988x over previous
#include <cuda_runtime.h>
#include <cuda_bf16.h>
#include <cstdint>
#include <math.h>

// Problem dims
#define BB   256
#define TT   200
#define DD   311
#define UU   256
#define G3   768          // 3*U
#define NOUT 19
#define BT   (BB*TT)      // 51200

typedef unsigned long long u64;

// ---------------- packed f32x2 helpers (Blackwell PTX) ---------------------
__device__ __forceinline__ u64 splat2(float v) {
    u64 r; unsigned u = __float_as_uint(v);
    asm("mov.b64 %0, {%1, %1};" : "=l"(r) : "r"(u));
    return r;
}
__device__ __forceinline__ void ffma2(u64& d, u64 a, u64 b) {
    asm("fma.rn.f32x2 %0, %1, %2, %0;" : "+l"(d) : "l"(a), "l"(b));
}
__device__ __forceinline__ float lo2(u64 v) {
    return __uint_as_float((unsigned)(v & 0xffffffffull));
}
__device__ __forceinline__ float hi2(u64 v) {
    return __uint_as_float((unsigned)(v >> 32));
}

// ---------------- cp.async / smem helpers ----------------------------------
__device__ __forceinline__ unsigned smem_u32(const void* p) {
    unsigned r;
    asm("{ .reg .u64 t; cvta.to.shared.u64 t, %1; cvt.u32.u64 %0, t; }"
        : "=r"(r) : "l"(p));
    return r;
}
#define CP16(dst, src) \
    asm volatile("cp.async.cg.shared.global [%0], [%1], 16;" :: "r"(dst), "l"(src))
#define CP4(dst, src) \
    asm volatile("cp.async.ca.shared.global [%0], [%1], 4;" :: "r"(dst), "l"(src))
#define CPCOMMIT() asm volatile("cp.async.commit_group;")
#define CPWAIT1()  asm volatile("cp.async.wait_group 1;" ::: "memory")
#define CPWAIT0()  asm volatile("cp.async.wait_group 0;" ::: "memory")

// spin until *addr != 0 with gpu-scope acquire (pairs with red.release below)
#define POLL_FLAG(addr) do {                                               \
    int _v;                                                                \
    do {                                                                   \
        asm volatile("ld.acquire.gpu.global.s32 %0, [%1];"                 \
                     : "=r"(_v) : "l"(addr) : "memory");                   \
        if (!_v) __nanosleep(24);                                          \
    } while (!_v);                                                         \
} while (0)

// ---------------- scratch (device globals; no cudaMalloc allowed) ----------
__device__ float g_xp[2][(size_t)BT * G3];   // input projections, per direction
__device__ float g_y [2][(size_t)BT * UU];   // hidden sequences
__device__ int   g_mask[BT];
__device__ float g_rkp2[2 * 8 * 96 * 256];   // rk col-major [dir][cc][col][k]
__device__ float g_b1p[2 * 8 * 96];          // recurrent bias per (dir, cc)
__device__ int   g_flags2[2 * 8 * TT * 8];   // [grp][step][producer cc]

// fast, accurate-enough gate functions (rel err ~2^-21)
__device__ __forceinline__ float fsig(float v) {
    return __fdividef(1.0f, 1.0f + __expf(-v));
}
__device__ __forceinline__ float ftanh(float v) {
    return 1.0f - __fdividef(2.0f, __expf(2.0f * v) + 1.0f);
}

// ---------------- mask: mask[b,t] = any(x[b,t,:] != 0) ---------------------
__global__ __launch_bounds__(256) void mask_kernel(const float* __restrict__ x) {
    int warp = (blockIdx.x * blockDim.x + threadIdx.x) >> 5;
    int lane = threadIdx.x & 31;
    if (warp >= BT) return;
    const float* row = x + (size_t)warp * DD;
    int any = 0;
    for (int i = lane; i < DD; i += 32) any |= (row[i] != 0.0f);
    unsigned b = __ballot_sync(0xffffffffu, any);
    if (lane == 0) g_mask[warp] = (b != 0u);
}

// ---------------- weight pre-pack: col-major per (dir, unit-chunk) ---------
__global__ __launch_bounds__(256) void pack_kernel(
    const float* __restrict__ rk_f, const float* __restrict__ rk_b,
    const float* __restrict__ b_f,  const float* __restrict__ b_b)
{
    int i = blockIdx.x * blockDim.x + threadIdx.x;
    const int total = 2 * 8 * 96 * 256;
    if (i < total) {
        int k     = i & 255;
        int rest  = i >> 8;
        int c     = rest % 96;
        int slice = rest / 96;          // 0..15
        int cc    = slice & 7;
        int dir   = slice >> 3;
        const float* rk = dir ? rk_b : rk_f;
        g_rkp2[i] = rk[(size_t)k * G3 + (c >> 5) * UU + cc * 32 + (c & 31)];
    }
    if (i < 2 * 8 * 96) {
        int c   = i % 96;
        int cc  = (i / 96) & 7;
        int dir = i / (96 * 8);
        const float* b = dir ? b_b : b_f;
        g_b1p[i] = b[G3 + (c >> 5) * UU + cc * 32 + (c & 31)];
    }
}

// ---------------- flag clear (graph replays need fresh flags) --------------
__global__ void clear_flags_kernel() {
    int i = blockIdx.x * blockDim.x + threadIdx.x;
    if (i < 2 * 8 * TT * 8) g_flags2[i] = 0;
}

// ---------------- phase 1: xp[m,n] = sum_k x[m,k]*W[k,n] + b0[n] -----------
// M=51200, K=311, N=768.  128x128x8 tile, 256 thr, 8x8 per-thread (f32x2),
// double-buffered smem with register prefetch.
#define NKT 39   // ceil(311/8)

__global__ __launch_bounds__(256) void proj_kernel(
    const float* __restrict__ x,
    const float* __restrict__ k_f, const float* __restrict__ b_f,
    const float* __restrict__ k_b, const float* __restrict__ b_b)
{
    __shared__ float As[2][8 * 132];
    __shared__ float Bs[2][8 * 132];

    const int dir = blockIdx.z;
    const float* W    = dir ? k_b : k_f;
    const float* bias = dir ? b_b : b_f;       // row 0 = input bias
    float* xp = g_xp[dir];

    const int m0 = blockIdx.y * 128;
    const int n0 = blockIdx.x * 128;
    const int tid = threadIdx.x;
    const int tx = tid & 15;
    const int ty = tid >> 4;

    const int lxm = tid >> 1;            // 0..127
    const int lxk = (tid & 1) * 4;       // 0 or 4
    const int lbk = tid >> 5;            // 0..7
    const int lbn = (tid & 31) * 4;      // 0..124

    float  xa[4];
    float4 wb;

    auto load_tile = [&](int k0) {
#pragma unroll
        for (int j = 0; j < 4; j++) {
            int k = k0 + lxk + j;
            xa[j] = (k < DD) ? __ldg(&x[(size_t)(m0 + lxm) * DD + k]) : 0.0f;
        }
        if (k0 + lbk < DD)
            wb = *(const float4*)&W[(size_t)(k0 + lbk) * G3 + n0 + lbn];
        else
            wb = make_float4(0.f, 0.f, 0.f, 0.f);
    };

    u64 acc2[8][4];
#pragma unroll
    for (int i = 0; i < 8; i++)
#pragma unroll
        for (int j = 0; j < 4; j++) acc2[i][j] = 0ull;

    load_tile(0);
#pragma unroll
    for (int j = 0; j < 4; j++) As[0][(lxk + j) * 132 + lxm] = xa[j];
    *(float4*)&Bs[0][lbk * 132 + lbn] = wb;
    __syncthreads();

    for (int tIdx = 0; tIdx < NKT; tIdx++) {
        const int cur = tIdx & 1;
        if (tIdx + 1 < NKT) load_tile((tIdx + 1) * 8);

#pragma unroll
        for (int kk = 0; kk < 8; kk++) {
            float4 a0 = *(float4*)&As[cur][kk * 132 + ty * 4];
            float4 a1 = *(float4*)&As[cur][kk * 132 + 64 + ty * 4];
            const u64* bp0 = (const u64*)&Bs[cur][kk * 132 + tx * 4];
            const u64* bp1 = (const u64*)&Bs[cur][kk * 132 + 64 + tx * 4];
            u64 bv[4] = {bp0[0], bp0[1], bp1[0], bp1[1]};
            float av[8] = {a0.x, a0.y, a0.z, a0.w, a1.x, a1.y, a1.z, a1.w};
#pragma unroll
            for (int i = 0; i < 8; i++) {
                u64 asp = splat2(av[i]);
#pragma unroll
                for (int j = 0; j < 4; j++) ffma2(acc2[i][j], asp, bv[j]);
            }
        }

        if (tIdx + 1 < NKT) {
            __syncthreads();
#pragma unroll
            for (int j = 0; j < 4; j++)
                As[cur ^ 1][(lxk + j) * 132 + lxm] = xa[j];
            *(float4*)&Bs[cur ^ 1][lbk * 132 + lbn] = wb;
            __syncthreads();
        }
    }

#pragma unroll
    for (int i = 0; i < 8; i++) {
        int row = m0 + ((i < 4) ? (ty * 4 + i) : (64 + ty * 4 + i - 4));
        float* o = &xp[(size_t)row * G3 + n0];
#pragma unroll
        for (int jh = 0; jh < 2; jh++) {
            int c0 = jh * 64 + tx * 4;
            float4 v;
            v.x = lo2(acc2[i][jh * 2 + 0]) + __ldg(&bias[n0 + c0 + 0]);
            v.y = hi2(acc2[i][jh * 2 + 0]) + __ldg(&bias[n0 + c0 + 1]);
            v.z = lo2(acc2[i][jh * 2 + 1]) + __ldg(&bias[n0 + c0 + 2]);
            v.w = hi2(acc2[i][jh * 2 + 1]) + __ldg(&bias[n0 + c0 + 3]);
            *(float4*)&o[c0] = v;
        }
    }
}

// ---------------- phase 2: persistent scan, chunked k-pipeline -------------
// grid = 128 CTAs, 256 thr, 171 KB smem -> 1 CTA/SM single wave (<=148),
// so the per-producer flag handshakes cannot deadlock.
// blockIdx.x = dir*64 + bg*8 + cc. rk slice pinned in smem.
// Per step, the 256-k GEMM is processed as 8 chunks of 32 k:
//   chunk cc (own units): h updated IN-PLACE in smem at gate time -> no wait.
//   peer chunks: per-producer flag poll + 4 KB cp.async.cg load, software-
//   pipelined under the previous chunk's GEMM. A slow peer delays only its
//   0.4 us chunk tail, not the whole step.
#define KS 260
#define SC2_FLOATS (96 * KS + 32 * KS + 32 * 100 + 2 * 3072 + 96 + 64)
#define SC2_BYTES  (SC2_FLOATS * 4)

__global__ __launch_bounds__(256) void scan_chunked()
{
    extern __shared__ float sm[];
    float* rs2  = sm;                       // [96][260] rk slice, col-major
    float* hs   = rs2 + 96 * KS;            // [32][260] h (full 256 units)
    float* recs = hs + 32 * KS;             // [32][100] rec + b1
    float* xpb  = recs + 32 * 100;          // [2][32][96] xp double buffer
    float* b1s  = xpb + 2 * 3072;           // [96]
    int*   mkv  = (int*)(b1s + 96);         // [2][32]

    const int tid = threadIdx.x;
    const int cc  = blockIdx.x & 7;
    const int bg  = (blockIdx.x >> 3) & 7;
    const int dir = blockIdx.x >> 6;
    const int u0  = cc * 32;
    const int b0  = bg * 32;

    float*       y  = g_y[dir];
    const float* xp = g_xp[dir];
    int* flags = g_flags2 + (size_t)(dir * 8 + bg) * TT * 8;

    const unsigned xpb_a = smem_u32(xpb);
    const unsigned mkv_a = smem_u32(mkv);
    const unsigned hs_a  = smem_u32(hs);

    // ---- one-time fills ----
    {   // rk slice: packed contiguous [96][256] -> smem stride-260 col-major
        const float4* src =
            (const float4*)(g_rkp2 + (size_t)(dir * 8 + cc) * 96 * 256);
#pragma unroll
        for (int i = 0; i < 24; i++) {
            int idx = tid + 256 * i;        // 96*64 = 6144 quads
            int c = idx >> 6, q = idx & 63;
            *(float4*)&rs2[c * KS + 4 * q] = src[idx];
        }
    }
    if (tid < 96) b1s[tid] = g_b1p[(dir * 8 + cc) * 96 + tid];
    for (int i = tid; i < 32 * KS; i += 256) hs[i] = 0.0f;    // h0 = 0

    // xp/mask prefetch for timestep tn into buffer buf
    auto prefetch = [&](int tn, int buf) {
        unsigned dbase = xpb_a + (unsigned)(buf * 3072) * 4u;
#pragma unroll
        for (int it = 0; it < 3; it++) {
            int j = tid + 256 * it;         // 0..767, 16B each
            int p = j >> 3, o = j & 7;
            int row = p / 3, seg = p - 3 * row;
            const float* src =
                xp + ((size_t)(b0 + row) * TT + tn) * G3 + seg * UU + u0 + o * 4;
            CP16(dbase + (unsigned)(row * 96 + seg * 32 + o * 4) * 4u, src);
        }
        if (tid < 32)
            CP4(mkv_a + (unsigned)(buf * 32 + tid) * 4u,
                &g_mask[(b0 + tid) * TT + tn]);
    };

    // 4 KB chunk load from y[tp]: one float4 per thread (32 rows x 8 quads)
    auto load_chunk = [&](int ko, int tp) {
        int rowi = tid >> 3, q = tid & 7;
        const float* src =
            &y[((size_t)(b0 + rowi) * TT + tp) * UU + ko * 32 + q * 4];
        CP16(hs_a + (unsigned)(rowi * KS + ko * 32 + q * 4) * 4u, src);
    };

    const int rt = tid & 15;              // GEMM rows {rt, rt+16}
    const int ct = tid >> 4;              // cols 6ct..6ct+5
    const int gr = tid >> 3;              // gates: row 0..31
    const int gu = (tid & 7) * 4;         // gates: 4 consecutive units

    // 32-k chunk GEMM accumulate
    auto gemm_chunk = [&](int ko, u64 (&acc)[2][6]) {
        const float* hp0 = &hs[rt * KS + ko * 32];
        const float* hp1 = &hs[(rt + 16) * KS + ko * 32];
        const float* wq  = &rs2[(6 * ct) * KS + ko * 32];
#pragma unroll
        for (int k0 = 0; k0 < 32; k0 += 4) {
            ulonglong2 ha = *(const ulonglong2*)(hp0 + k0);
            ulonglong2 hc = *(const ulonglong2*)(hp1 + k0);
#pragma unroll
            for (int j = 0; j < 6; j++) {
                ulonglong2 w = *(const ulonglong2*)(wq + j * KS + k0);
                ffma2(acc[0][j], ha.x, w.x);
                ffma2(acc[0][j], ha.y, w.y);
                ffma2(acc[1][j], hc.x, w.x);
                ffma2(acc[1][j], hc.y, w.y);
            }
        }
    };

    prefetch(dir ? (TT - 1) : 0, 0);      // xp for s=0
    CPCOMMIT();
    __syncthreads();

    for (int s = 0; s < TT; s++) {
        const int t  = dir ? (TT - 1 - s) : s;
        const int tp = dir ? (t + 1) : (t - 1);       // valid when s > 0
        const int* fprev = flags + (size_t)(s - 1) * 8;

        if (s + 1 < TT) prefetch(dir ? (t - 1) : (t + 1), (s + 1) & 1);
        CPCOMMIT();                                    // xp group

        if (s > 0) {                                   // start first peer chunk
            int k1 = (cc + 1) & 7;
            if (tid == 0) POLL_FLAG(fprev + k1);
            __syncthreads();
            load_chunk(k1, tp);
            CPCOMMIT();
        }

        u64 acc[2][6];
#pragma unroll
        for (int i = 0; i < 2; i++)
#pragma unroll
            for (int j = 0; j < 6; j++) acc[i][j] = 0ull;

        gemm_chunk(cc, acc);                           // own chunk: no wait

        if (s > 0) {
            for (int j = 1; j < 8; j++) {
                int kc = (cc + j) & 7;
                if (j < 7) {
                    int kn = (cc + j + 1) & 7;
                    if (tid == 0) POLL_FLAG(fprev + kn);
                }
                __syncthreads();                       // flag seen by all
                if (j < 7) {
                    int kn = (cc + j + 1) & 7;
                    load_chunk(kn, tp);
                    CPCOMMIT();
                    CPWAIT1();                         // chunk kc landed
                } else {
                    CPWAIT0();                         // last chunk + xp done
                }
                __syncthreads();
                gemm_chunk(kc, acc);
            }
        } else {
            CPWAIT0();                                 // xp for gates(s=0)
            __syncthreads();
        }

        // rec + recurrent bias -> smem exchange (GEMM->gate remap)
#pragma unroll
        for (int i = 0; i < 2; i++) {
            int row = rt + 16 * i;
#pragma unroll
            for (int j = 0; j < 6; j++)
                recs[row * 100 + 6 * ct + j] =
                    lo2(acc[i][j]) + hi2(acc[i][j]) + b1s[6 * ct + j];
        }
        __syncthreads();

        // ---- gates: 1 row x 4 units; write y + in-place hs (own chunk) ----
        {
            const float* xb = &xpb[(s & 1) * 3072];
            float4 rz = *(float4*)&recs[gr * 100 + gu];
            float4 rr = *(float4*)&recs[gr * 100 + 32 + gu];
            float4 rh = *(float4*)&recs[gr * 100 + 64 + gu];
            float4 xz = *(const float4*)&xb[gr * 96 + gu];
            float4 xr = *(const float4*)&xb[gr * 96 + 32 + gu];
            float4 xh = *(const float4*)&xb[gr * 96 + 64 + gu];
            float4 hp = *(const float4*)&hs[gr * KS + u0 + gu];
            int msk = mkv[(s & 1) * 32 + gr];

            float4 hn;
            {
                float z0 = fsig(xz.x + rz.x), z1 = fsig(xz.y + rz.y);
                float z2 = fsig(xz.z + rz.z), z3 = fsig(xz.w + rz.w);
                float r0 = fsig(xr.x + rr.x), r1 = fsig(xr.y + rr.y);
                float r2 = fsig(xr.z + rr.z), r3 = fsig(xr.w + rr.w);
                float h0 = ftanh(xh.x + r0 * rh.x), h1 = ftanh(xh.y + r1 * rh.y);
                float h2 = ftanh(xh.z + r2 * rh.z), h3 = ftanh(xh.w + r3 * rh.w);
                hn.x = z0 * hp.x + (1.0f - z0) * h0;
                hn.y = z1 * hp.y + (1.0f - z1) * h1;
                hn.z = z2 * hp.z + (1.0f - z2) * h2;
                hn.w = z3 * hp.w + (1.0f - z3) * h3;
            }
            if (!msk) hn = hp;

            *(float4*)&y[((size_t)(b0 + gr) * TT + t) * UU + u0 + gu] = hn;
            *(float4*)&hs[gr * KS + u0 + gu] = hn;     // own chunk for s+1
        }

        __syncthreads();                               // y stores + hs update
        if (tid == 0) {
            asm volatile("red.add.release.gpu.global.s32 [%0], 1;"
                         :: "l"(flags + (size_t)s * 8 + cc) : "memory");
        }
    }
}

// ---------------- phase 3: dense + softmax ---------------------------------
__global__ __launch_bounds__(256) void dense_kernel(
    const float* __restrict__ w_d, const float* __restrict__ b_d,
    float* __restrict__ out)
{
    __shared__ float ws[2 * UU * NOUT];   // 512*19
    __shared__ float bs[NOUT];
    for (int i = threadIdx.x; i < 2 * UU * NOUT; i += 256) ws[i] = w_d[i];
    if (threadIdx.x < NOUT) bs[threadIdx.x] = b_d[threadIdx.x];
    __syncthreads();

    int warp = threadIdx.x >> 5, lane = threadIdx.x & 31;
    int row = blockIdx.x * 8 + warp;               // 6400 * 8 = 51200 exact
    const float* hf = g_y[0] + (size_t)row * UU;
    const float* hb = g_y[1] + (size_t)row * UU;

    float acc[NOUT];
#pragma unroll
    for (int o = 0; o < NOUT; o++) acc[o] = 0.0f;

    for (int j = lane; j < UU; j += 32) {
        float a = hf[j];
        const float* w = &ws[j * NOUT];
#pragma unroll
        for (int o = 0; o < NOUT; o++) acc[o] += a * w[o];
        float b = hb[j];
        const float* w2 = &ws[(UU + j) * NOUT];
#pragma unroll
        for (int o = 0; o < NOUT; o++) acc[o] += b * w2[o];
    }
#pragma unroll
    for (int off = 16; off > 0; off >>= 1)
#pragma unroll
        for (int o = 0; o < NOUT; o++)
            acc[o] += __shfl_xor_sync(0xffffffffu, acc[o], off);

#pragma unroll
    for (int o = 0; o < NOUT; o++) acc[o] += bs[o];
    float m = acc[0];
#pragma unroll
    for (int o = 1; o < NOUT; o++) m = fmaxf(m, acc[o]);
    float sum = 0.0f;
#pragma unroll
    for (int o = 0; o < NOUT; o++) { acc[o] = expf(acc[o] - m); sum += acc[o]; }
    float inv = 1.0f / sum;

    if (lane < NOUT) {
        float v = 0.0f;
#pragma unroll
        for (int o = 0; o < NOUT; o++) if (lane == o) v = acc[o];
        out[(size_t)row * NOUT + lane] = v * inv;
    }
}

// ---------------- launch ----------------------------------------------------
extern "C" void kernel_launch(void* const* d_in, const int* in_sizes, int n_in,
                              void* d_out, int out_size)
{
    const float* x    = (const float*)d_in[0];
    const float* k_f  = (const float*)d_in[1];
    const float* rk_f = (const float*)d_in[2];
    const float* b_f  = (const float*)d_in[3];
    const float* k_b  = (const float*)d_in[4];
    const float* rk_b = (const float*)d_in[5];
    const float* b_b  = (const float*)d_in[6];
    const float* w_d  = (const float*)d_in[7];
    const float* b_d  = (const float*)d_in[8];
    float* out = (float*)d_out;

    // mask + weight pack + flag clear + input projections
    mask_kernel<<<BT / 8, 256>>>(x);
    pack_kernel<<<(2 * 8 * 96 * 256) / 256, 256>>>(rk_f, rk_b, b_f, b_b);
    clear_flags_kernel<<<100, 256>>>();
    dim3 pg(G3 / 128, BT / 128, 2);
    proj_kernel<<<pg, 256>>>(x, k_f, b_f, k_b, b_b);

    // persistent chunked scan: 128 CTAs, 1/SM single wave, 200 steps
    cudaFuncSetAttribute(scan_chunked,
                         cudaFuncAttributeMaxDynamicSharedMemorySize,
                         SC2_BYTES);
    scan_chunked<<<128, 256, SC2_BYTES>>>();

    // dense + softmax
    dense_kernel<<<BT / 8, 256>>>(w_d, b_d, out);
}